// round 1
// baseline (speedup 1.0000x reference)
#include <cuda_runtime.h>
#include <math.h>

// Fixed problem shape: S=8192, B=2, H=2048, O=2048
//   M = S*B = 16384, K = H = 2048, N = O = 2048
// Scratch for the masked (2:4 sparse) weight. 2048*2048 floats = 16 MB.
__device__ float g_wsp[2048 * 2048];

// ---------------------------------------------------------------------------
// Kernel 1: N:M mask (N=2 keep, M=4 group). Zero the 2 smallest-|w| per group
// of 4, replicating stable argsort order (first occurrence of min zeroed first).
// ---------------------------------------------------------------------------
__global__ void nm_mask_kernel(const float* __restrict__ w, int n_groups) {
    int g = blockIdx.x * blockDim.x + threadIdx.x;
    if (g >= n_groups) return;
    float4 v = reinterpret_cast<const float4*>(w)[g];
    float vals[4] = {v.x, v.y, v.z, v.w};
    float a[4] = {fabsf(v.x), fabsf(v.y), fabsf(v.z), fabsf(v.w)};

    // first smallest (strict < keeps first occurrence on ties -> stable)
    int z1 = 0;
    #pragma unroll
    for (int i = 1; i < 4; i++) if (a[i] < a[z1]) z1 = i;
    a[z1] = INFINITY;
    // second smallest
    int z2 = 0;
    #pragma unroll
    for (int i = 1; i < 4; i++) if (a[i] < a[z2]) z2 = i;

    vals[z1] = 0.0f;
    vals[z2] = 0.0f;
    reinterpret_cast<float4*>(g_wsp)[g] =
        make_float4(vals[0], vals[1], vals[2], vals[3]);
}

// ---------------------------------------------------------------------------
// Kernel 2: FP32 NT GEMM. C[M,N] = A[M,K] * W[N,K]^T + bias[N]
// Block tile 128x128, K-tile 16, 256 threads, 8x8 per-thread micro-tile.
// Both A and W are K-major, loaded as float4 and transposed into smem.
// ---------------------------------------------------------------------------
#define BM 128
#define BN 128
#define BK 16
#define TM 8
#define TN 8
#define SPAD 132   // padded row length in floats (kills transpose bank conflicts)

__global__ __launch_bounds__(256, 2)
void sgemm_nt_kernel(const float* __restrict__ A,
                     const float* __restrict__ bias,
                     float* __restrict__ C,
                     int M, int N, int K) {
    __shared__ float As[BK][SPAD];
    __shared__ float Bs[BK][SPAD];

    const float* W = g_wsp;

    const int tid = threadIdx.x;
    const int bm = blockIdx.y;   // M block
    const int bn = blockIdx.x;   // N block

    const float* Ablk = A + (size_t)bm * BM * K;
    const float* Bblk = W + (size_t)bn * BN * K;

    // loader mapping: 4 threads per row (16 floats = 4 float4), 64 rows/pass
    const int rowL = tid >> 2;          // 0..63
    const int colL = (tid & 3) * 4;     // 0,4,8,12

    // compute mapping
    const int ty = tid >> 4;            // 0..15 -> M
    const int tx = tid & 15;            // 0..15 -> N

    float acc[TM][TN];
    #pragma unroll
    for (int i = 0; i < TM; i++)
        #pragma unroll
        for (int j = 0; j < TN; j++)
            acc[i][j] = 0.0f;

    for (int k0 = 0; k0 < K; k0 += BK) {
        #pragma unroll
        for (int r = 0; r < 2; r++) {
            int row = rowL + r * 64;
            float4 va = *reinterpret_cast<const float4*>(
                Ablk + (size_t)row * K + k0 + colL);
            As[colL + 0][row] = va.x;
            As[colL + 1][row] = va.y;
            As[colL + 2][row] = va.z;
            As[colL + 3][row] = va.w;
            float4 vb = *reinterpret_cast<const float4*>(
                Bblk + (size_t)row * K + k0 + colL);
            Bs[colL + 0][row] = vb.x;
            Bs[colL + 1][row] = vb.y;
            Bs[colL + 2][row] = vb.z;
            Bs[colL + 3][row] = vb.w;
        }
        __syncthreads();

        #pragma unroll
        for (int k = 0; k < BK; k++) {
            float rm[TM], rn[TN];
            float4 m0 = *reinterpret_cast<const float4*>(&As[k][ty * TM]);
            float4 m1 = *reinterpret_cast<const float4*>(&As[k][ty * TM + 4]);
            rm[0] = m0.x; rm[1] = m0.y; rm[2] = m0.z; rm[3] = m0.w;
            rm[4] = m1.x; rm[5] = m1.y; rm[6] = m1.z; rm[7] = m1.w;
            float4 n0 = *reinterpret_cast<const float4*>(&Bs[k][tx * TN]);
            float4 n1 = *reinterpret_cast<const float4*>(&Bs[k][tx * TN + 4]);
            rn[0] = n0.x; rn[1] = n0.y; rn[2] = n0.z; rn[3] = n0.w;
            rn[4] = n1.x; rn[5] = n1.y; rn[6] = n1.z; rn[7] = n1.w;

            #pragma unroll
            for (int i = 0; i < TM; i++)
                #pragma unroll
                for (int j = 0; j < TN; j++)
                    acc[i][j] = fmaf(rm[i], rn[j], acc[i][j]);
        }
        __syncthreads();
    }

    // epilogue: + bias, vectorized stores
    const int rowBase = bm * BM + ty * TM;
    const int colBase = bn * BN + tx * TN;
    float rbias[TN];
    #pragma unroll
    for (int j = 0; j < TN; j++) rbias[j] = bias[colBase + j];

    #pragma unroll
    for (int i = 0; i < TM; i++) {
        float* crow = C + (size_t)(rowBase + i) * N + colBase;
        float4 o0, o1;
        o0.x = acc[i][0] + rbias[0];
        o0.y = acc[i][1] + rbias[1];
        o0.z = acc[i][2] + rbias[2];
        o0.w = acc[i][3] + rbias[3];
        o1.x = acc[i][4] + rbias[4];
        o1.y = acc[i][5] + rbias[5];
        o1.z = acc[i][6] + rbias[6];
        o1.w = acc[i][7] + rbias[7];
        *reinterpret_cast<float4*>(crow) = o0;
        *reinterpret_cast<float4*>(crow + 4) = o1;
    }
}

// ---------------------------------------------------------------------------
// Launch
// ---------------------------------------------------------------------------
extern "C" void kernel_launch(void* const* d_in, const int* in_sizes, int n_in,
                              void* d_out, int out_size) {
    const float* x    = (const float*)d_in[0];  // [S,B,H] = [M,K]
    const float* w    = (const float*)d_in[1];  // [O,H]   = [N,K]
    const float* bias = (const float*)d_in[2];  // [O]
    float* out = (float*)d_out;                 // [M,N]

    const int O = in_sizes[2];              // 2048
    const int H = in_sizes[1] / O;          // 2048
    const int M = in_sizes[0] / H;          // 16384

    // 1) build sparse weight
    int n_groups = in_sizes[1] / 4;
    nm_mask_kernel<<<(n_groups + 255) / 256, 256>>>(w, n_groups);

    // 2) GEMM + bias
    dim3 grid(O / BN, M / BM);
    sgemm_nt_kernel<<<grid, 256>>>(x, bias, out, M, O, H);
}

// round 3
// speedup vs baseline: 3.0406x; 3.0406x over previous
#include <cuda_runtime.h>
#include <cuda_bf16.h>
#include <math.h>
#include <stdint.h>

// ===========================================================================
// out[M,N] = x[M,K] @ (w * nm_mask(w))[N,K]^T + bias[N]
// M=16384, N=2048, K=2048 fp32.
// bf16 hi/lo split, 3-pass mma.sync (HMMA) with fp32 accumulators.
// ===========================================================================

__device__ __nv_bfloat16 g_xhi[16384 * 2048];
__device__ __nv_bfloat16 g_xlo[16384 * 2048];
__device__ __nv_bfloat16 g_whi[2048 * 2048];
__device__ __nv_bfloat16 g_wlo[2048 * 2048];

// ---------------- helpers ---------------------------------------------------
__device__ __forceinline__ uint32_t smem_u32(const void* p) {
    uint32_t a;
    asm("{ .reg .u64 t; cvta.to.shared.u64 t, %1; cvt.u32.u64 %0, t; }"
        : "=r"(a) : "l"(p));
    return a;
}
__device__ __forceinline__ void cp16(uint32_t sm, const void* g) {
    asm volatile("cp.async.cg.shared.global [%0], [%1], 16;" :: "r"(sm), "l"(g));
}
#define CP_COMMIT() asm volatile("cp.async.commit_group;" ::: "memory")
#define CP_WAIT1()  asm volatile("cp.async.wait_group 1;"  ::: "memory")
#define CP_WAIT0()  asm volatile("cp.async.wait_group 0;"  ::: "memory")

__device__ __forceinline__ void ldm4(uint32_t r[4], uint32_t addr) {
    asm volatile("ldmatrix.sync.aligned.m8n8.x4.shared.b16 {%0,%1,%2,%3}, [%4];"
                 : "=r"(r[0]), "=r"(r[1]), "=r"(r[2]), "=r"(r[3]) : "r"(addr));
}
__device__ __forceinline__ void mma16816(float c[4], const uint32_t a[4],
                                         const uint32_t b0, const uint32_t b1) {
    asm volatile(
        "mma.sync.aligned.m16n8k16.row.col.f32.bf16.bf16.f32 "
        "{%0,%1,%2,%3}, {%4,%5,%6,%7}, {%8,%9}, {%0,%1,%2,%3};"
        : "+f"(c[0]), "+f"(c[1]), "+f"(c[2]), "+f"(c[3])
        : "r"(a[0]), "r"(a[1]), "r"(a[2]), "r"(a[3]), "r"(b0), "r"(b1));
}

// ---------------- GEMM config ----------------------------------------------
#define BM 128
#define BN 128
#define BKE 64               // bf16 elems per k-chunk = 128 B per row
#define NTH 256
#define STG_A_HI 0
#define STG_A_LO 16384
#define STG_B_HI 32768
#define STG_B_LO 49152
#define STAGE_SZ 65536
#define SMEM_TOTAL 131072

// ===========================================================================
// Kernel 1: 2:4 mask (stable-argsort semantics) + bf16 hi/lo split of weight
// ===========================================================================
__global__ void prep_w_kernel(const float* __restrict__ w, int n_groups) {
    int g = blockIdx.x * blockDim.x + threadIdx.x;
    if (g >= n_groups) return;
    float4 v = reinterpret_cast<const float4*>(w)[g];
    float vals[4] = {v.x, v.y, v.z, v.w};
    float a[4] = {fabsf(v.x), fabsf(v.y), fabsf(v.z), fabsf(v.w)};
    int z1 = 0;
    #pragma unroll
    for (int i = 1; i < 4; i++) if (a[i] < a[z1]) z1 = i;
    a[z1] = INFINITY;
    int z2 = 0;
    #pragma unroll
    for (int i = 1; i < 4; i++) if (a[i] < a[z2]) z2 = i;
    vals[z1] = 0.0f;
    vals[z2] = 0.0f;

    __nv_bfloat16 hi[4], lo[4];
    #pragma unroll
    for (int i = 0; i < 4; i++) {
        hi[i] = __float2bfloat16(vals[i]);
        lo[i] = __float2bfloat16(vals[i] - __bfloat162float(hi[i]));
    }
    __nv_bfloat162 h01(hi[0], hi[1]), h23(hi[2], hi[3]);
    __nv_bfloat162 l01(lo[0], lo[1]), l23(lo[2], lo[3]);
    uint2 uh, ul;
    uh.x = *reinterpret_cast<uint32_t*>(&h01);
    uh.y = *reinterpret_cast<uint32_t*>(&h23);
    ul.x = *reinterpret_cast<uint32_t*>(&l01);
    ul.y = *reinterpret_cast<uint32_t*>(&l23);
    reinterpret_cast<uint2*>(g_whi)[g] = uh;
    reinterpret_cast<uint2*>(g_wlo)[g] = ul;
}

// ===========================================================================
// Kernel 2: bf16 hi/lo split of x
// ===========================================================================
__global__ void prep_x_kernel(const float* __restrict__ x, int n_quads) {
    int g = blockIdx.x * blockDim.x + threadIdx.x;
    if (g >= n_quads) return;
    float4 v = reinterpret_cast<const float4*>(x)[g];
    float vals[4] = {v.x, v.y, v.z, v.w};
    __nv_bfloat16 hi[4], lo[4];
    #pragma unroll
    for (int i = 0; i < 4; i++) {
        hi[i] = __float2bfloat16(vals[i]);
        lo[i] = __float2bfloat16(vals[i] - __bfloat162float(hi[i]));
    }
    __nv_bfloat162 h01(hi[0], hi[1]), h23(hi[2], hi[3]);
    __nv_bfloat162 l01(lo[0], lo[1]), l23(lo[2], lo[3]);
    uint2 uh, ul;
    uh.x = *reinterpret_cast<uint32_t*>(&h01);
    uh.y = *reinterpret_cast<uint32_t*>(&h23);
    ul.x = *reinterpret_cast<uint32_t*>(&l01);
    ul.y = *reinterpret_cast<uint32_t*>(&l23);
    reinterpret_cast<uint2*>(g_xhi)[g] = uh;
    reinterpret_cast<uint2*>(g_xlo)[g] = ul;
}

// ===========================================================================
// Kernel 3: mma.sync bf16x3 GEMM.  grid=(N/128, M/128), 256 threads.
// smem tiles: 128 rows x 128B, SW128-style XOR swizzle (ldmatrix conflict-free)
// ===========================================================================
__device__ __forceinline__ void load_stage(uint32_t sb, int stage, int chunk,
                                           int bm, int bn, int tid, int K) {
    const int k0 = chunk * BKE;
    const uint32_t st = sb + stage * STAGE_SZ;
    #pragma unroll
    for (int t = tid; t < 1024; t += NTH) {
        int row = t >> 3, c = t & 7;
        uint32_t so = (uint32_t)(row << 7) + (((c ^ (row & 7)) << 4));
        size_t ga = (size_t)(bm * BM + row) * K + k0 + c * 8;
        cp16(st + STG_A_HI + so, g_xhi + ga);
        cp16(st + STG_A_LO + so, g_xlo + ga);
        size_t gb = (size_t)(bn * BN + row) * K + k0 + c * 8;
        cp16(st + STG_B_HI + so, g_whi + gb);
        cp16(st + STG_B_LO + so, g_wlo + gb);
    }
}

__global__ __launch_bounds__(NTH, 1)
void gemm_mma_kernel(const float* __restrict__ bias,
                     float* __restrict__ C,
                     int M, int N, int K) {
    extern __shared__ char smem[];
    const uint32_t sb = smem_u32(smem);
    const int tid = threadIdx.x;
    const int wid = tid >> 5;
    const int lid = tid & 31;
    const int bn = blockIdx.x;
    const int bm = blockIdx.y;

    const int wm = wid >> 2;          // 0..1 -> 64-row band
    const int wn = wid & 3;           // 0..3 -> 32-col band

    // ldmatrix lane address components
    const int a_r  = lid & 15;        // A row within m16 tile
    const int a_ch = lid >> 4;        // A 16B col within k16 (0/1)
    const int b_r  = (lid & 7) + ((lid >> 4) << 3);  // B row within n16 tile
    const int b_ch = (lid >> 3) & 1;  // B 16B col within k16

    float acc[4][4][4];
    #pragma unroll
    for (int i = 0; i < 4; i++)
        #pragma unroll
        for (int j = 0; j < 4; j++)
            #pragma unroll
            for (int r = 0; r < 4; r++)
                acc[i][j][r] = 0.0f;

    const int NIT = K / BKE;          // 32
    load_stage(sb, 0, 0, bm, bn, tid, K);
    CP_COMMIT();
    load_stage(sb, 1, 1, bm, bn, tid, K);
    CP_COMMIT();

    for (int i = 0; i < NIT; i++) {
        const int s = i & 1;
        CP_WAIT1();
        __syncthreads();
        const uint32_t Ah = sb + s * STAGE_SZ + STG_A_HI;
        const uint32_t Al = sb + s * STAGE_SZ + STG_A_LO;
        const uint32_t Bh = sb + s * STAGE_SZ + STG_B_HI;
        const uint32_t Bl = sb + s * STAGE_SZ + STG_B_LO;

        #pragma unroll
        for (int kk = 0; kk < 4; kk++) {
            uint32_t ahf[4][4], alf[4][4], bhf[4][2], blf[4][2];
            #pragma unroll
            for (int mt = 0; mt < 4; mt++) {
                int row = wm * 64 + mt * 16 + a_r;
                int c = (kk << 1) + a_ch;
                uint32_t off = (uint32_t)(row << 7) + (((c ^ (row & 7)) << 4));
                ldm4(ahf[mt], Ah + off);
                ldm4(alf[mt], Al + off);
            }
            #pragma unroll
            for (int bt = 0; bt < 2; bt++) {
                int row = wn * 32 + bt * 16 + b_r;
                int c = (kk << 1) + b_ch;
                uint32_t off = (uint32_t)(row << 7) + (((c ^ (row & 7)) << 4));
                uint32_t rh[4], rl[4];
                ldm4(rh, Bh + off);
                ldm4(rl, Bl + off);
                bhf[2 * bt + 0][0] = rh[0]; bhf[2 * bt + 0][1] = rh[1];
                bhf[2 * bt + 1][0] = rh[2]; bhf[2 * bt + 1][1] = rh[3];
                blf[2 * bt + 0][0] = rl[0]; blf[2 * bt + 0][1] = rl[1];
                blf[2 * bt + 1][0] = rl[2]; blf[2 * bt + 1][1] = rl[3];
            }
            #pragma unroll
            for (int mt = 0; mt < 4; mt++)
                #pragma unroll
                for (int nt = 0; nt < 4; nt++) {
                    mma16816(acc[mt][nt], ahf[mt], bhf[nt][0], bhf[nt][1]);
                    mma16816(acc[mt][nt], ahf[mt], blf[nt][0], blf[nt][1]);
                    mma16816(acc[mt][nt], alf[mt], bhf[nt][0], bhf[nt][1]);
                }
        }
        __syncthreads();
        if (i + 2 < NIT) load_stage(sb, s, i + 2, bm, bn, tid, K);
        CP_COMMIT();
    }

    // ---------------- epilogue: regs -> smem -> coalesced +bias stores ------
    CP_WAIT0();
    __syncthreads();
    float* stg = reinterpret_cast<float*>(smem);
    #pragma unroll
    for (int mt = 0; mt < 4; mt++)
        #pragma unroll
        for (int nt = 0; nt < 4; nt++) {
            int r0 = wm * 64 + mt * 16 + (lid >> 2);
            int col = wn * 32 + nt * 8 + ((lid & 3) << 1);
            stg[r0 * 132 + col + 0] = acc[mt][nt][0];
            stg[r0 * 132 + col + 1] = acc[mt][nt][1];
            stg[(r0 + 8) * 132 + col + 0] = acc[mt][nt][2];
            stg[(r0 + 8) * 132 + col + 1] = acc[mt][nt][3];
        }
    __syncthreads();
    #pragma unroll
    for (int t = tid; t < 4096; t += NTH) {
        int row = t >> 5;
        int c4 = (t & 31) << 2;
        float4 v = *reinterpret_cast<float4*>(&stg[row * 132 + c4]);
        float4 b4 = *reinterpret_cast<const float4*>(bias + bn * BN + c4);
        v.x += b4.x; v.y += b4.y; v.z += b4.z; v.w += b4.w;
        *reinterpret_cast<float4*>(
            C + (size_t)(bm * BM + row) * N + bn * BN + c4) = v;
    }
}

// ===========================================================================
// Launch
// ===========================================================================
extern "C" void kernel_launch(void* const* d_in, const int* in_sizes, int n_in,
                              void* d_out, int out_size) {
    const float* x    = (const float*)d_in[0];  // [M,K]
    const float* w    = (const float*)d_in[1];  // [N,K]
    const float* bias = (const float*)d_in[2];  // [N]
    float* out = (float*)d_out;                 // [M,N]

    const int O = in_sizes[2];          // 2048
    const int H = in_sizes[1] / O;      // 2048
    const int M = in_sizes[0] / H;      // 16384

    int wg = O * H / 4;
    prep_w_kernel<<<(wg + 255) / 256, 256>>>(w, wg);
    int xg = M * H / 4;
    prep_x_kernel<<<(xg + 255) / 256, 256>>>(x, xg);

    cudaFuncSetAttribute(gemm_mma_kernel,
                         cudaFuncAttributeMaxDynamicSharedMemorySize, SMEM_TOTAL);
    dim3 grid(O / BN, M / BM);
    gemm_mma_kernel<<<grid, NTH, SMEM_TOTAL>>>(bias, out, M, O, H);
}

// round 4
// speedup vs baseline: 7.2940x; 2.3989x over previous
#include <cuda_runtime.h>
#include <cuda_fp16.h>
#include <math.h>
#include <stdint.h>

// ===========================================================================
// out[M,N] = x[M,K] @ (w * nm_mask(w))[N,K]^T + bias[N]
// M=16384, N=2048, K=2048 fp32.
// Single-pass fp16 mma.sync (fp32 accum). rel_err ~2e-4 < 1e-3.
// ===========================================================================

__device__ __half g_xh[16384 * 2048];
__device__ __half g_wh[2048 * 2048];

// ---------------- helpers ---------------------------------------------------
__device__ __forceinline__ uint32_t smem_u32(const void* p) {
    uint32_t a;
    asm("{ .reg .u64 t; cvta.to.shared.u64 t, %1; cvt.u32.u64 %0, t; }"
        : "=r"(a) : "l"(p));
    return a;
}
__device__ __forceinline__ void cp16(uint32_t sm, const void* g) {
    asm volatile("cp.async.cg.shared.global [%0], [%1], 16;" :: "r"(sm), "l"(g));
}
#define CP_COMMIT() asm volatile("cp.async.commit_group;" ::: "memory")
#define CP_WAIT2()  asm volatile("cp.async.wait_group 2;"  ::: "memory")
#define CP_WAIT0()  asm volatile("cp.async.wait_group 0;"  ::: "memory")

__device__ __forceinline__ void ldm4(uint32_t r[4], uint32_t addr) {
    asm volatile("ldmatrix.sync.aligned.m8n8.x4.shared.b16 {%0,%1,%2,%3}, [%4];"
                 : "=r"(r[0]), "=r"(r[1]), "=r"(r[2]), "=r"(r[3]) : "r"(addr));
}
__device__ __forceinline__ void mma16816(float c[4], const uint32_t a[4],
                                         const uint32_t b0, const uint32_t b1) {
    asm volatile(
        "mma.sync.aligned.m16n8k16.row.col.f32.f16.f16.f32 "
        "{%0,%1,%2,%3}, {%4,%5,%6,%7}, {%8,%9}, {%0,%1,%2,%3};"
        : "+f"(c[0]), "+f"(c[1]), "+f"(c[2]), "+f"(c[3])
        : "r"(a[0]), "r"(a[1]), "r"(a[2]), "r"(a[3]), "r"(b0), "r"(b1));
}

// ---------------- GEMM config ----------------------------------------------
#define BM 128
#define BN 256
#define BKE 64               // fp16 elems per k-chunk = 128 B/row
#define NTH 256
#define NSTAGE 4
#define STG_A 0              // 16 KB (128 rows x 128 B)
#define STG_B 16384          // 32 KB (256 rows x 128 B)
#define STAGE_SZ 49152
#define SMEM_TOTAL (NSTAGE * STAGE_SZ)   // 192 KB

// ===========================================================================
// Kernel 1: 2:4 mask (stable-argsort semantics) + fp16 convert of weight
// ===========================================================================
__global__ void prep_w_kernel(const float* __restrict__ w, int n_groups) {
    int g = blockIdx.x * blockDim.x + threadIdx.x;
    if (g >= n_groups) return;
    float4 v = reinterpret_cast<const float4*>(w)[g];
    float vals[4] = {v.x, v.y, v.z, v.w};
    float a[4] = {fabsf(v.x), fabsf(v.y), fabsf(v.z), fabsf(v.w)};
    int z1 = 0;
    #pragma unroll
    for (int i = 1; i < 4; i++) if (a[i] < a[z1]) z1 = i;
    a[z1] = INFINITY;
    int z2 = 0;
    #pragma unroll
    for (int i = 1; i < 4; i++) if (a[i] < a[z2]) z2 = i;
    vals[z1] = 0.0f;
    vals[z2] = 0.0f;

    __half h[4];
    #pragma unroll
    for (int i = 0; i < 4; i++) h[i] = __float2half(vals[i]);
    uint2 u;
    __half2 h01(h[0], h[1]), h23(h[2], h[3]);
    u.x = *reinterpret_cast<uint32_t*>(&h01);
    u.y = *reinterpret_cast<uint32_t*>(&h23);
    reinterpret_cast<uint2*>(g_wh)[g] = u;
}

// ===========================================================================
// Kernel 2: fp16 convert of x
// ===========================================================================
__global__ void prep_x_kernel(const float* __restrict__ x, int n_quads) {
    int g = blockIdx.x * blockDim.x + threadIdx.x;
    if (g >= n_quads) return;
    float4 v = reinterpret_cast<const float4*>(x)[g];
    __half h[4] = {__float2half(v.x), __float2half(v.y),
                   __float2half(v.z), __float2half(v.w)};
    uint2 u;
    __half2 h01(h[0], h[1]), h23(h[2], h[3]);
    u.x = *reinterpret_cast<uint32_t*>(&h01);
    u.y = *reinterpret_cast<uint32_t*>(&h23);
    reinterpret_cast<uint2*>(g_xh)[g] = u;
}

// ===========================================================================
// Kernel 3: fp16 mma.sync GEMM. grid=(N/256, M/128), 256 threads (8 warps).
// Warp layout 2x4; warp tile 64x64. 4-stage cp.async ring. SW128 xor swizzle.
// ===========================================================================
__device__ __forceinline__ void load_stage(uint32_t sb, int slot, int chunk,
                                           int bm, int bn, int tid, int K) {
    const int k0 = chunk * BKE;
    const uint32_t st = sb + slot * STAGE_SZ;
    #pragma unroll
    for (int t = tid; t < 1024; t += NTH) {       // A: 128 rows x 8 chunks
        int row = t >> 3, c = t & 7;
        uint32_t so = (uint32_t)(row << 7) + ((c ^ (row & 7)) << 4);
        size_t ga = (size_t)(bm * BM + row) * K + k0 + c * 8;
        cp16(st + STG_A + so, g_xh + ga);
    }
    #pragma unroll
    for (int t = tid; t < 2048; t += NTH) {       // B: 256 rows x 8 chunks
        int row = t >> 3, c = t & 7;
        uint32_t so = (uint32_t)(row << 7) + ((c ^ (row & 7)) << 4);
        size_t gb = (size_t)(bn * BN + row) * K + k0 + c * 8;
        cp16(st + STG_B + so, g_wh + gb);
    }
}

__global__ __launch_bounds__(NTH, 1)
void gemm_mma_kernel(const float* __restrict__ bias,
                     float* __restrict__ C,
                     int M, int N, int K) {
    extern __shared__ char smem[];
    const uint32_t sb = smem_u32(smem);
    const int tid = threadIdx.x;
    const int wid = tid >> 5;
    const int lid = tid & 31;
    const int bn = blockIdx.x;
    const int bm = blockIdx.y;

    const int wm = wid >> 2;          // 0..1 -> 64-row band
    const int wn = wid & 3;           // 0..3 -> 64-col band

    const int a_r  = lid & 15;
    const int a_ch = lid >> 4;
    const int b_r  = (lid & 7) + ((lid >> 4) << 3);
    const int b_ch = (lid >> 3) & 1;

    float acc[4][8][4];
    #pragma unroll
    for (int i = 0; i < 4; i++)
        #pragma unroll
        for (int j = 0; j < 8; j++)
            #pragma unroll
            for (int r = 0; r < 4; r++)
                acc[i][j][r] = 0.0f;

    const int NIT = K / BKE;          // 32
    load_stage(sb, 0, 0, bm, bn, tid, K); CP_COMMIT();
    load_stage(sb, 1, 1, bm, bn, tid, K); CP_COMMIT();
    load_stage(sb, 2, 2, bm, bn, tid, K); CP_COMMIT();

    for (int i = 0; i < NIT; i++) {
        const int s = i & 3;
        CP_WAIT2();
        __syncthreads();
        const uint32_t A = sb + s * STAGE_SZ + STG_A;
        const uint32_t B = sb + s * STAGE_SZ + STG_B;

        #pragma unroll
        for (int kk = 0; kk < 4; kk++) {
            uint32_t af[4][4], bf[8][2];
            #pragma unroll
            for (int mt = 0; mt < 4; mt++) {
                int row = wm * 64 + mt * 16 + a_r;
                int c = (kk << 1) + a_ch;
                uint32_t off = (uint32_t)(row << 7) + ((c ^ (row & 7)) << 4);
                ldm4(af[mt], A + off);
            }
            #pragma unroll
            for (int bt = 0; bt < 4; bt++) {
                int row = wn * 64 + bt * 16 + b_r;
                int c = (kk << 1) + b_ch;
                uint32_t off = (uint32_t)(row << 7) + ((c ^ (row & 7)) << 4);
                uint32_t rb[4];
                ldm4(rb, B + off);
                bf[2 * bt + 0][0] = rb[0]; bf[2 * bt + 0][1] = rb[1];
                bf[2 * bt + 1][0] = rb[2]; bf[2 * bt + 1][1] = rb[3];
            }
            #pragma unroll
            for (int mt = 0; mt < 4; mt++)
                #pragma unroll
                for (int nt = 0; nt < 8; nt++)
                    mma16816(acc[mt][nt], af[mt], bf[nt][0], bf[nt][1]);
        }
        __syncthreads();
        if (i + 3 < NIT) load_stage(sb, (i + 3) & 3, i + 3, bm, bn, tid, K);
        CP_COMMIT();
    }

    // ---------------- epilogue: regs -> smem -> coalesced +bias stores ------
    CP_WAIT0();
    __syncthreads();
    float* stg = reinterpret_cast<float*>(smem);
    #pragma unroll
    for (int mt = 0; mt < 4; mt++)
        #pragma unroll
        for (int nt = 0; nt < 8; nt++) {
            int r0 = wm * 64 + mt * 16 + (lid >> 2);
            int col = wn * 64 + nt * 8 + ((lid & 3) << 1);
            stg[r0 * 260 + col + 0] = acc[mt][nt][0];
            stg[r0 * 260 + col + 1] = acc[mt][nt][1];
            stg[(r0 + 8) * 260 + col + 0] = acc[mt][nt][2];
            stg[(r0 + 8) * 260 + col + 1] = acc[mt][nt][3];
        }
    __syncthreads();
    #pragma unroll
    for (int t = tid; t < 8192; t += NTH) {
        int row = t >> 6;
        int c4 = (t & 63) << 2;
        float4 v = *reinterpret_cast<float4*>(&stg[row * 260 + c4]);
        float4 b4 = *reinterpret_cast<const float4*>(bias + bn * BN + c4);
        v.x += b4.x; v.y += b4.y; v.z += b4.z; v.w += b4.w;
        *reinterpret_cast<float4*>(
            C + (size_t)(bm * BM + row) * N + bn * BN + c4) = v;
    }
}

// ===========================================================================
// Launch
// ===========================================================================
extern "C" void kernel_launch(void* const* d_in, const int* in_sizes, int n_in,
                              void* d_out, int out_size) {
    const float* x    = (const float*)d_in[0];  // [M,K]
    const float* w    = (const float*)d_in[1];  // [N,K]
    const float* bias = (const float*)d_in[2];  // [N]
    float* out = (float*)d_out;                 // [M,N]

    const int O = in_sizes[2];          // 2048
    const int H = in_sizes[1] / O;      // 2048
    const int M = in_sizes[0] / H;      // 16384

    int wg = O * H / 4;
    prep_w_kernel<<<(wg + 255) / 256, 256>>>(w, wg);
    int xg = M * H / 4;
    prep_x_kernel<<<(xg + 255) / 256, 256>>>(x, xg);

    cudaFuncSetAttribute(gemm_mma_kernel,
                         cudaFuncAttributeMaxDynamicSharedMemorySize, SMEM_TOTAL);
    dim3 grid(O / BN, M / BM);
    gemm_mma_kernel<<<grid, NTH, SMEM_TOTAL>>>(bias, out, M, O, H);
}